// round 4
// baseline (speedup 1.0000x reference)
#include <cuda_runtime.h>
#include <cuda_bf16.h>

// GNNEncoder: B=8, N=10000, F_IN=128, H=128, E=160000
#define NB     8
#define NNODES 10000
#define HDIM   128
#define BH     (NB * HDIM)        // 1024
#define EMAX   160000

// ---------------- device scratch (static globals: sanctioned by harness) ---
__device__ float d_t1[NNODES * BH];   // gemm1 out, [N][B][H]
__device__ float d_h1[NNODES * BH];   // relu(agg1 + b1), [N][B][H]
__device__ float d_t2[NNODES * BH];   // gemm2 out, [N][B][H]
__device__ int   d_cnt[NNODES];
__device__ int   d_beg[NNODES];
__device__ int   d_cur[NNODES];
__device__ float d_dinv[NNODES];
__device__ int   d_csr[EMAX];
__device__ int   d_total;
__device__ int   d_is64;              // 1 if edge_index stored as int64 words

// ---------------- setup ----------------------------------------------------
// Detect whether edge buffer is int64 (odd 32-bit words all zero) or int32.
__global__ void detectKernel(const int* __restrict__ ei, int E) {
    if (threadIdx.x == 0 && blockIdx.x == 0) {
        int allzero = 1;
        for (int i = 0; i < 64; i++) {
            if (ei[2 * i + 1] != 0) { allzero = 0; break; }
        }
        d_is64 = allzero;
        d_total = 0;
    }
}

__global__ void initCntKernel() {
    int i = blockIdx.x * blockDim.x + threadIdx.x;
    if (i < NNODES) d_cnt[i] = 0;
}

__global__ void countDegKernel(const int* __restrict__ ei, int E) {
    int e = blockIdx.x * blockDim.x + threadIdx.x;
    if (e < E) {
        int stride = d_is64 ? 2 : 1;
        int dst = ei[(size_t)stride * (E + e)];
        if ((unsigned)dst < NNODES) atomicAdd(&d_cnt[dst], 1);
    }
}

// per-node contiguous CSR range via one atomic allocation (no scan needed)
__global__ void baseKernel() {
    int n = blockIdx.x * blockDim.x + threadIdx.x;
    if (n < NNODES) {
        int c = d_cnt[n];
        int base = atomicAdd(&d_total, c);
        d_beg[n] = base;
        d_cur[n] = base;
        d_dinv[n] = rsqrtf((float)(c + 1));   // +1 for self loop
    }
}

__global__ void fillCsrKernel(const int* __restrict__ ei, int E) {
    int e = blockIdx.x * blockDim.x + threadIdx.x;
    if (e < E) {
        int stride = d_is64 ? 2 : 1;
        int src = ei[(size_t)stride * e];
        int dst = ei[(size_t)stride * (E + e)];
        if ((unsigned)src < NNODES && (unsigned)dst < NNODES) {
            int p = atomicAdd(&d_cur[dst], 1);
            if ((unsigned)p < EMAX) d_csr[p] = src;
        }
    }
}

// ---------------- GEMM1: t1[n][b][:] = x[b][n][:] @ W1 ---------------------
// block = 4 nodes x 8 batches = 32 rows, 128 cols. 256 threads.
// thread: 4 rows x 4 cols (16 fp32 accumulators), ~1B LDS per FFMA.
__global__ void __launch_bounds__(256) gemm1Kernel(const float4* __restrict__ x4,
                                                   const float4* __restrict__ W4) {
    __shared__ float4 xs4[32][32];       // 32 rows x 128 floats
    int n0 = blockIdx.x * 4;
    int t = threadIdx.x;

#pragma unroll
    for (int k = 0; k < 4; k++) {
        int e = k * 256 + t;
        int r = e >> 5;                  // row 0..31
        int f4 = e & 31;
        int i = r >> 3;                  // local node
        int b = r & 7;                   // batch
        xs4[r][f4] = x4[((size_t)b * NNODES + (n0 + i)) * 32 + f4];
    }
    __syncthreads();

    int c4 = t & 31;                     // col group: cols 4*c4 .. 4*c4+3
    int rg = t >> 5;                     // row group: rows rg*4 .. rg*4+3
    float4 acc0 = {0.f, 0.f, 0.f, 0.f};
    float4 acc1 = {0.f, 0.f, 0.f, 0.f};
    float4 acc2 = {0.f, 0.f, 0.f, 0.f};
    float4 acc3 = {0.f, 0.f, 0.f, 0.f};

    for (int f4 = 0; f4 < 32; f4++) {
        float4 w0 = W4[(4 * f4 + 0) * 32 + c4];
        float4 w1 = W4[(4 * f4 + 1) * 32 + c4];
        float4 w2 = W4[(4 * f4 + 2) * 32 + c4];
        float4 w3 = W4[(4 * f4 + 3) * 32 + c4];
        float4 xv0 = xs4[rg * 4 + 0][f4];
        float4 xv1 = xs4[rg * 4 + 1][f4];
        float4 xv2 = xs4[rg * 4 + 2][f4];
        float4 xv3 = xs4[rg * 4 + 3][f4];

        acc0.x += xv0.x * w0.x + xv0.y * w1.x + xv0.z * w2.x + xv0.w * w3.x;
        acc0.y += xv0.x * w0.y + xv0.y * w1.y + xv0.z * w2.y + xv0.w * w3.y;
        acc0.z += xv0.x * w0.z + xv0.y * w1.z + xv0.z * w2.z + xv0.w * w3.z;
        acc0.w += xv0.x * w0.w + xv0.y * w1.w + xv0.z * w2.w + xv0.w * w3.w;

        acc1.x += xv1.x * w0.x + xv1.y * w1.x + xv1.z * w2.x + xv1.w * w3.x;
        acc1.y += xv1.x * w0.y + xv1.y * w1.y + xv1.z * w2.y + xv1.w * w3.y;
        acc1.z += xv1.x * w0.z + xv1.y * w1.z + xv1.z * w2.z + xv1.w * w3.z;
        acc1.w += xv1.x * w0.w + xv1.y * w1.w + xv1.z * w2.w + xv1.w * w3.w;

        acc2.x += xv2.x * w0.x + xv2.y * w1.x + xv2.z * w2.x + xv2.w * w3.x;
        acc2.y += xv2.x * w0.y + xv2.y * w1.y + xv2.z * w2.y + xv2.w * w3.y;
        acc2.z += xv2.x * w0.z + xv2.y * w1.z + xv2.z * w2.z + xv2.w * w3.z;
        acc2.w += xv2.x * w0.w + xv2.y * w1.w + xv2.z * w2.w + xv2.w * w3.w;

        acc3.x += xv3.x * w0.x + xv3.y * w1.x + xv3.z * w2.x + xv3.w * w3.x;
        acc3.y += xv3.x * w0.y + xv3.y * w1.y + xv3.z * w2.y + xv3.w * w3.y;
        acc3.z += xv3.x * w0.z + xv3.y * w1.z + xv3.z * w2.z + xv3.w * w3.z;
        acc3.w += xv3.x * w0.w + xv3.y * w1.w + xv3.z * w2.w + xv3.w * w3.w;
    }

    float4* out4 = (float4*)d_t1;
#pragma unroll
    for (int rr = 0; rr < 4; rr++) {
        int r = rg * 4 + rr;
        int i = r >> 3;
        int b = r & 7;
        float4 v = (rr == 0) ? acc0 : (rr == 1) ? acc1 : (rr == 2) ? acc2 : acc3;
        out4[((size_t)(n0 + i) * NB + b) * 32 + c4] = v;
    }
}

// ---------------- GEMM2: t2[n][b][:] = h1[n][b][:] @ W2 --------------------
__global__ void __launch_bounds__(256) gemm2Kernel(const float4* __restrict__ W4) {
    __shared__ float4 xs4[32][32];
    int n0 = blockIdx.x * 4;
    int t = threadIdx.x;
    const float4* h4 = (const float4*)d_h1;

#pragma unroll
    for (int k = 0; k < 4; k++) {
        int e = k * 256 + t;
        int r = e >> 5;
        int f4 = e & 31;
        int i = r >> 3;
        int b = r & 7;
        xs4[r][f4] = h4[((size_t)(n0 + i) * NB + b) * 32 + f4];
    }
    __syncthreads();

    int c4 = t & 31;
    int rg = t >> 5;
    float4 acc0 = {0.f, 0.f, 0.f, 0.f};
    float4 acc1 = {0.f, 0.f, 0.f, 0.f};
    float4 acc2 = {0.f, 0.f, 0.f, 0.f};
    float4 acc3 = {0.f, 0.f, 0.f, 0.f};

    for (int f4 = 0; f4 < 32; f4++) {
        float4 w0 = W4[(4 * f4 + 0) * 32 + c4];
        float4 w1 = W4[(4 * f4 + 1) * 32 + c4];
        float4 w2 = W4[(4 * f4 + 2) * 32 + c4];
        float4 w3 = W4[(4 * f4 + 3) * 32 + c4];
        float4 xv0 = xs4[rg * 4 + 0][f4];
        float4 xv1 = xs4[rg * 4 + 1][f4];
        float4 xv2 = xs4[rg * 4 + 2][f4];
        float4 xv3 = xs4[rg * 4 + 3][f4];

        acc0.x += xv0.x * w0.x + xv0.y * w1.x + xv0.z * w2.x + xv0.w * w3.x;
        acc0.y += xv0.x * w0.y + xv0.y * w1.y + xv0.z * w2.y + xv0.w * w3.y;
        acc0.z += xv0.x * w0.z + xv0.y * w1.z + xv0.z * w2.z + xv0.w * w3.z;
        acc0.w += xv0.x * w0.w + xv0.y * w1.w + xv0.z * w2.w + xv0.w * w3.w;

        acc1.x += xv1.x * w0.x + xv1.y * w1.x + xv1.z * w2.x + xv1.w * w3.x;
        acc1.y += xv1.x * w0.y + xv1.y * w1.y + xv1.z * w2.y + xv1.w * w3.y;
        acc1.z += xv1.x * w0.z + xv1.y * w1.z + xv1.z * w2.z + xv1.w * w3.z;
        acc1.w += xv1.x * w0.w + xv1.y * w1.w + xv1.z * w2.w + xv1.w * w3.w;

        acc2.x += xv2.x * w0.x + xv2.y * w1.x + xv2.z * w2.x + xv2.w * w3.x;
        acc2.y += xv2.x * w0.y + xv2.y * w1.y + xv2.z * w2.y + xv2.w * w3.y;
        acc2.z += xv2.x * w0.z + xv2.y * w1.z + xv2.z * w2.z + xv2.w * w3.z;
        acc2.w += xv2.x * w0.w + xv2.y * w1.w + xv2.z * w2.w + xv2.w * w3.w;

        acc3.x += xv3.x * w0.x + xv3.y * w1.x + xv3.z * w2.x + xv3.w * w3.x;
        acc3.y += xv3.x * w0.y + xv3.y * w1.y + xv3.z * w2.y + xv3.w * w3.y;
        acc3.z += xv3.x * w0.z + xv3.y * w1.z + xv3.z * w2.z + xv3.w * w3.z;
        acc3.w += xv3.x * w0.w + xv3.y * w1.w + xv3.z * w2.w + xv3.w * w3.w;
    }

    float4* out4 = (float4*)d_t2;
#pragma unroll
    for (int rr = 0; rr < 4; rr++) {
        int r = rg * 4 + rr;
        int i = r >> 3;
        int b = r & 7;
        float4 v = (rr == 0) ? acc0 : (rr == 1) ? acc1 : (rr == 2) ? acc2 : acc3;
        out4[((size_t)(n0 + i) * NB + b) * 32 + c4] = v;
    }
}

// ---------------- aggregation (gather) -------------------------------------
// grid (N, 4), 256 threads: block covers node n = blockIdx.x,
// columns [blockIdx.y*256, blockIdx.y*256+256) of the 1024 (b,h) lanes.
__device__ __forceinline__ float agg_gather(const float* __restrict__ tin,
                                            int n, int col) {
    float dn = d_dinv[n];
    int beg = d_beg[n];
    int end = beg + d_cnt[n];
    float a0 = 0.f, a1 = 0.f, a2 = 0.f, a3 = 0.f;
    int e = beg;
    for (; e + 4 <= end; e += 4) {
        int s0 = d_csr[e + 0];
        int s1 = d_csr[e + 1];
        int s2 = d_csr[e + 2];
        int s3 = d_csr[e + 3];
        float w0 = d_dinv[s0];
        float w1 = d_dinv[s1];
        float w2 = d_dinv[s2];
        float w3 = d_dinv[s3];
        a0 += w0 * tin[(size_t)s0 * BH + col];
        a1 += w1 * tin[(size_t)s1 * BH + col];
        a2 += w2 * tin[(size_t)s2 * BH + col];
        a3 += w3 * tin[(size_t)s3 * BH + col];
    }
    for (; e < end; e++) {
        int s = d_csr[e];
        a0 += d_dinv[s] * tin[(size_t)s * BH + col];
    }
    float acc = ((a0 + a1) + (a2 + a3)) * dn;
    acc += dn * dn * tin[(size_t)n * BH + col];   // self loop
    return acc;
}

__global__ void __launch_bounds__(256) aggReluKernel(const float* __restrict__ bias) {
    int n = blockIdx.x;
    int col = blockIdx.y * 256 + threadIdx.x;
    float v = agg_gather(d_t1, n, col) + bias[col & 127];
    d_h1[(size_t)n * BH + col] = fmaxf(v, 0.f);
}

__global__ void __launch_bounds__(256) aggLNKernel(const float* __restrict__ bias,
                                                   const float* __restrict__ lnw,
                                                   const float* __restrict__ lnb,
                                                   float* __restrict__ out) {
    int n = blockIdx.x;
    int t = threadIdx.x;
    int h = t & 127;
    int b = blockIdx.y * 2 + (t >> 7);            // block covers 2 batch rows
    float v = agg_gather(d_t2, n, blockIdx.y * 256 + t) + bias[h];

    // LayerNorm over each 128-lane group (4 warps)
    __shared__ float red[8];
    int lane = t & 31;
    int wid = t >> 5;
    int g4 = (t >> 7) * 4;

    float s = v;
#pragma unroll
    for (int off = 16; off > 0; off >>= 1) s += __shfl_down_sync(0xffffffffu, s, off);
    if (lane == 0) red[wid] = s;
    __syncthreads();
    float mean = (red[g4] + red[g4 + 1] + red[g4 + 2] + red[g4 + 3]) * (1.f / 128.f);
    float d = v - mean;
    __syncthreads();

    float s2 = d * d;
#pragma unroll
    for (int off = 16; off > 0; off >>= 1) s2 += __shfl_down_sync(0xffffffffu, s2, off);
    if (lane == 0) red[wid] = s2;
    __syncthreads();
    float var = (red[g4] + red[g4 + 1] + red[g4 + 2] + red[g4 + 3]) * (1.f / 128.f);

    out[((size_t)b * NNODES + n) * HDIM + h] = d * rsqrtf(var + 1e-5f) * lnw[h] + lnb[h];
}

// ---------------- launch ---------------------------------------------------
extern "C" void kernel_launch(void* const* d_in, const int* in_sizes, int n_in,
                              void* d_out, int out_size) {
    const float4* x4  = (const float4*)d_in[0];
    const int*    ei  = (const int*)d_in[1];     // int32 OR int64 (auto-detect)
    const float4* W1  = (const float4*)d_in[2];
    const float*  b1  = (const float*)d_in[3];
    const float4* W2  = (const float4*)d_in[4];
    const float*  b2  = (const float*)d_in[5];
    const float*  lnw = (const float*)d_in[6];
    const float*  lnb = (const float*)d_in[7];
    float*        out = (float*)d_out;

    int E = in_sizes[1] / 2;
    if (E > EMAX) E = EMAX;

    detectKernel<<<1, 32>>>(ei, E);
    initCntKernel<<<(NNODES + 255) / 256, 256>>>();
    countDegKernel<<<(E + 255) / 256, 256>>>(ei, E);
    baseKernel<<<(NNODES + 255) / 256, 256>>>();
    fillCsrKernel<<<(E + 255) / 256, 256>>>(ei, E);

    gemm1Kernel<<<NNODES / 4, 256>>>(x4, W1);
    aggReluKernel<<<dim3(NNODES, 4), 256>>>(b1);
    gemm2Kernel<<<NNODES / 4, 256>>>(W2);
    aggLNKernel<<<dim3(NNODES, 4), 256>>>(b2, lnw, lnb, out);
}

// round 5
// speedup vs baseline: 2.2576x; 2.2576x over previous
#include <cuda_runtime.h>
#include <cuda_bf16.h>

// GNNEncoder: B=8, N=10000, F_IN=128, H=128, E=160000
#define NB     8
#define NNODES 10000
#define HDIM   128
#define BH     (NB * HDIM)        // 1024
#define BH4    (BH / 4)           // 256 float4 per node row
#define EMAX   160000

typedef unsigned long long u64;

// ---------------- device scratch (16B-aligned via float4) ------------------
__device__ float4 d_t1[NNODES * BH4];   // gemm1 out, [N][B][H]
__device__ float4 d_h1[NNODES * BH4];   // relu(agg1 + b1), [N][B][H]
__device__ float4 d_t2[NNODES * BH4];   // gemm2 out, [N][B][H]
__device__ int    d_cnt[NNODES];
__device__ int    d_beg[NNODES];
__device__ int    d_cur[NNODES];
__device__ float  d_dinv[NNODES];
__device__ int    d_csr[EMAX];
__device__ int    d_total;
__device__ int    d_is64;               // 1 if edge_index stored as int64 words

// ---------------- packed fp32x2 helpers ------------------------------------
__device__ __forceinline__ u64 pack_dup(float x) {
    u64 r;
    asm("mov.b64 %0, {%1, %1};" : "=l"(r) : "f"(x));
    return r;
}
__device__ __forceinline__ void fma2(u64& acc, u64 a, u64 b) {
    asm("fma.rn.f32x2 %0, %1, %2, %0;" : "+l"(acc) : "l"(a), "l"(b));
}

// ---------------- setup ----------------------------------------------------
__global__ void initKernel(const int* __restrict__ ei) {
    int i = blockIdx.x * blockDim.x + threadIdx.x;
    if (i < NNODES) d_cnt[i] = 0;
    if (i == 0) {
        int allzero = 1;
        for (int k = 0; k < 64; k++)
            if (ei[2 * k + 1] != 0) { allzero = 0; break; }
        d_is64 = allzero;          // int64 values < 2^31: odd words all zero
        d_total = 0;
    }
}

__global__ void countDegKernel(const int* __restrict__ ei, int E) {
    int e = blockIdx.x * blockDim.x + threadIdx.x;
    if (e < E) {
        int stride = d_is64 ? 2 : 1;
        int dst = ei[(size_t)stride * (E + e)];
        if ((unsigned)dst < NNODES) atomicAdd(&d_cnt[dst], 1);
    }
}

__global__ void baseKernel() {
    int n = blockIdx.x * blockDim.x + threadIdx.x;
    if (n < NNODES) {
        int c = d_cnt[n];
        int base = atomicAdd(&d_total, c);
        d_beg[n] = base;
        d_cur[n] = base;
        d_dinv[n] = rsqrtf((float)(c + 1));   // +1 for self loop
    }
}

__global__ void fillCsrKernel(const int* __restrict__ ei, int E) {
    int e = blockIdx.x * blockDim.x + threadIdx.x;
    if (e < E) {
        int stride = d_is64 ? 2 : 1;
        int src = ei[(size_t)stride * e];
        int dst = ei[(size_t)stride * (E + e)];
        if ((unsigned)src < NNODES && (unsigned)dst < NNODES) {
            int p = atomicAdd(&d_cur[dst], 1);
            if ((unsigned)p < EMAX) d_csr[p] = src;
        }
    }
}

// ---------------- GEMMs with packed fp32x2 ---------------------------------
// block = 4 nodes x 8 batches = 32 rows, 128 cols, 256 threads.
// thread: 4 rows x 4 cols; accumulators held as f32x2 pairs.
__device__ __forceinline__ void gemm_core(const float4 xs4[32][32],
                                          const ulonglong2* __restrict__ Wv,
                                          ulonglong2* __restrict__ outv,
                                          int n0, int t) {
    int c4 = t & 31;                  // col group: cols 4*c4 .. 4*c4+3
    int rg = t >> 5;                  // row group: rows rg*4 .. rg*4+3
    u64 acc[4][2];
#pragma unroll
    for (int r = 0; r < 4; r++) { acc[r][0] = 0ull; acc[r][1] = 0ull; }

    for (int f4 = 0; f4 < 32; f4++) {
        ulonglong2 w0 = Wv[(4 * f4 + 0) * 32 + c4];
        ulonglong2 w1 = Wv[(4 * f4 + 1) * 32 + c4];
        ulonglong2 w2 = Wv[(4 * f4 + 2) * 32 + c4];
        ulonglong2 w3 = Wv[(4 * f4 + 3) * 32 + c4];
#pragma unroll
        for (int rr = 0; rr < 4; rr++) {
            float4 xv = xs4[rg * 4 + rr][f4];
            u64 dA = pack_dup(xv.x);
            u64 dB = pack_dup(xv.y);
            u64 dC = pack_dup(xv.z);
            u64 dD = pack_dup(xv.w);
            fma2(acc[rr][0], dA, w0.x); fma2(acc[rr][1], dA, w0.y);
            fma2(acc[rr][0], dB, w1.x); fma2(acc[rr][1], dB, w1.y);
            fma2(acc[rr][0], dC, w2.x); fma2(acc[rr][1], dC, w2.y);
            fma2(acc[rr][0], dD, w3.x); fma2(acc[rr][1], dD, w3.y);
        }
    }

#pragma unroll
    for (int rr = 0; rr < 4; rr++) {
        int r = rg * 4 + rr;
        int i = r >> 3;
        int b = r & 7;
        ulonglong2 v; v.x = acc[rr][0]; v.y = acc[rr][1];
        outv[((size_t)(n0 + i) * NB + b) * 32 + c4] = v;
    }
}

__global__ void __launch_bounds__(256) gemm1Kernel(const float4* __restrict__ x4,
                                                   const ulonglong2* __restrict__ Wv) {
    __shared__ float4 xs4[32][32];
    int n0 = blockIdx.x * 4;
    int t = threadIdx.x;
#pragma unroll
    for (int k = 0; k < 4; k++) {
        int e = k * 256 + t;
        int r = e >> 5, f4 = e & 31;
        int i = r >> 3, b = r & 7;
        xs4[r][f4] = x4[((size_t)b * NNODES + (n0 + i)) * 32 + f4];
    }
    __syncthreads();
    gemm_core(xs4, Wv, (ulonglong2*)d_t1, n0, t);
}

__global__ void __launch_bounds__(256) gemm2Kernel(const ulonglong2* __restrict__ Wv) {
    __shared__ float4 xs4[32][32];
    int n0 = blockIdx.x * 4;
    int t = threadIdx.x;
#pragma unroll
    for (int k = 0; k < 4; k++) {
        int e = k * 256 + t;
        int r = e >> 5, f4 = e & 31;
        int i = r >> 3, b = r & 7;
        xs4[r][f4] = d_h1[((size_t)(n0 + i) * NB + b) * 32 + f4];
    }
    __syncthreads();
    gemm_core(xs4, Wv, (ulonglong2*)d_t2, n0, t);
}

// ---------------- aggregation (float4 gather, one block per node) ----------
__device__ __forceinline__ float4 agg_gather4(const float4* __restrict__ tin4,
                                              int n, int c4) {
    float dn = d_dinv[n];
    int beg = d_beg[n];
    int end = beg + d_cnt[n];
    float4 a0 = {0.f, 0.f, 0.f, 0.f};
    float4 a1 = {0.f, 0.f, 0.f, 0.f};
    float4 a2 = {0.f, 0.f, 0.f, 0.f};
    float4 a3 = {0.f, 0.f, 0.f, 0.f};
    int e = beg;
    for (; e + 4 <= end; e += 4) {
        int s0 = d_csr[e + 0];
        int s1 = d_csr[e + 1];
        int s2 = d_csr[e + 2];
        int s3 = d_csr[e + 3];
        float w0 = d_dinv[s0];
        float w1 = d_dinv[s1];
        float w2 = d_dinv[s2];
        float w3 = d_dinv[s3];
        float4 v0 = tin4[(size_t)s0 * BH4 + c4];
        float4 v1 = tin4[(size_t)s1 * BH4 + c4];
        float4 v2 = tin4[(size_t)s2 * BH4 + c4];
        float4 v3 = tin4[(size_t)s3 * BH4 + c4];
        a0.x += w0 * v0.x; a0.y += w0 * v0.y; a0.z += w0 * v0.z; a0.w += w0 * v0.w;
        a1.x += w1 * v1.x; a1.y += w1 * v1.y; a1.z += w1 * v1.z; a1.w += w1 * v1.w;
        a2.x += w2 * v2.x; a2.y += w2 * v2.y; a2.z += w2 * v2.z; a2.w += w2 * v2.w;
        a3.x += w3 * v3.x; a3.y += w3 * v3.y; a3.z += w3 * v3.z; a3.w += w3 * v3.w;
    }
    for (; e < end; e++) {
        int s = d_csr[e];
        float w = d_dinv[s];
        float4 v = tin4[(size_t)s * BH4 + c4];
        a0.x += w * v.x; a0.y += w * v.y; a0.z += w * v.z; a0.w += w * v.w;
    }
    float4 self = tin4[(size_t)n * BH4 + c4];
    float sw = dn * dn;
    float4 r;
    r.x = (((a0.x + a1.x) + (a2.x + a3.x))) * dn + sw * self.x;
    r.y = (((a0.y + a1.y) + (a2.y + a3.y))) * dn + sw * self.y;
    r.z = (((a0.z + a1.z) + (a2.z + a3.z))) * dn + sw * self.z;
    r.w = (((a0.w + a1.w) + (a2.w + a3.w))) * dn + sw * self.w;
    return r;
}

__global__ void __launch_bounds__(256) aggReluKernel(const float4* __restrict__ bias4) {
    int n = blockIdx.x;
    int c4 = threadIdx.x;                    // cols 4*c4..4*c4+3 of 1024
    float4 v = agg_gather4(d_t1, n, c4);
    float4 bb = bias4[c4 & 31];              // bias over h = col % 128
    v.x = fmaxf(v.x + bb.x, 0.f);
    v.y = fmaxf(v.y + bb.y, 0.f);
    v.z = fmaxf(v.z + bb.z, 0.f);
    v.w = fmaxf(v.w + bb.w, 0.f);
    d_h1[(size_t)n * BH4 + c4] = v;
}

// warp w owns row (n, b=w): lanes hold h = 4*lane .. 4*lane+3
__global__ void __launch_bounds__(256) aggLNKernel(const float4* __restrict__ bias4,
                                                   const float4* __restrict__ lnw4,
                                                   const float4* __restrict__ lnb4,
                                                   float4* __restrict__ out4) {
    int n = blockIdx.x;
    int t = threadIdx.x;
    int lane = t & 31;
    int b = t >> 5;
    float4 v = agg_gather4(d_t2, n, t);
    float4 bb = bias4[lane];
    v.x += bb.x; v.y += bb.y; v.z += bb.z; v.w += bb.w;

    float s = (v.x + v.y) + (v.z + v.w);
#pragma unroll
    for (int off = 16; off > 0; off >>= 1) s += __shfl_xor_sync(0xffffffffu, s, off);
    float mean = s * (1.f / 128.f);

    float4 d;
    d.x = v.x - mean; d.y = v.y - mean; d.z = v.z - mean; d.w = v.w - mean;
    float s2 = (d.x * d.x + d.y * d.y) + (d.z * d.z + d.w * d.w);
#pragma unroll
    for (int off = 16; off > 0; off >>= 1) s2 += __shfl_xor_sync(0xffffffffu, s2, off);
    float rs = rsqrtf(s2 * (1.f / 128.f) + 1e-5f);

    float4 w = lnw4[lane];
    float4 bo = lnb4[lane];
    float4 r;
    r.x = d.x * rs * w.x + bo.x;
    r.y = d.y * rs * w.y + bo.y;
    r.z = d.z * rs * w.z + bo.z;
    r.w = d.w * rs * w.w + bo.w;
    out4[((size_t)b * NNODES + n) * 32 + lane] = r;
}

// ---------------- launch ---------------------------------------------------
extern "C" void kernel_launch(void* const* d_in, const int* in_sizes, int n_in,
                              void* d_out, int out_size) {
    const float4*     x4  = (const float4*)d_in[0];
    const int*        ei  = (const int*)d_in[1];     // int32 OR int64 (auto)
    const ulonglong2* W1  = (const ulonglong2*)d_in[2];
    const float4*     b1  = (const float4*)d_in[3];
    const ulonglong2* W2  = (const ulonglong2*)d_in[4];
    const float4*     b2  = (const float4*)d_in[5];
    const float4*     lnw = (const float4*)d_in[6];
    const float4*     lnb = (const float4*)d_in[7];
    float4*           out = (float4*)d_out;

    int E = in_sizes[1] / 2;
    if (E > EMAX) E = EMAX;

    initKernel<<<(NNODES + 255) / 256, 256>>>(ei);
    countDegKernel<<<(E + 255) / 256, 256>>>(ei, E);
    baseKernel<<<(NNODES + 255) / 256, 256>>>();
    fillCsrKernel<<<(E + 255) / 256, 256>>>(ei, E);

    gemm1Kernel<<<NNODES / 4, 256>>>(x4, W1);
    aggReluKernel<<<NNODES, 256>>>(b1);
    gemm2Kernel<<<NNODES / 4, 256>>>(W2);
    aggLNKernel<<<NNODES, 256>>>(b2, lnw, lnb, out);
}

// round 6
// speedup vs baseline: 2.3932x; 1.0601x over previous
#include <cuda_runtime.h>
#include <cuda_fp16.h>

// GNNEncoder: B=8, N=10000, F_IN=128, H=128, E=160000
#define NB     8
#define NNODES 10000
#define HDIM   128
#define BH     (NB * HDIM)        // 1024
#define BH4    (BH / 4)           // 256 groups of 4 cols per node row
#define EMAX   160000

typedef unsigned long long u64;

// ---------------- device scratch -------------------------------------------
// t1, t2: fp16, 4 halves per uint2 -> [N][256] uint2 (gather operands)
// h1: fp32 (never gathered through a GEMM in fp16 -> keeps precision)
__device__ uint2  d_t1[NNODES * BH4];
__device__ float4 d_h1[NNODES * BH4];
__device__ uint2  d_t2[NNODES * BH4];
__device__ int    d_cnt[NNODES];
__device__ int    d_beg[NNODES];
__device__ int    d_cur[NNODES];
__device__ float  d_dinv[NNODES];
__device__ int    d_csr[EMAX];
__device__ int    d_total;
__device__ int    d_is64;               // 1 if edge_index stored as int64 words

// ---------------- packed helpers -------------------------------------------
__device__ __forceinline__ u64 pack_dup(float x) {
    u64 r;
    asm("mov.b64 %0, {%1, %1};" : "=l"(r) : "f"(x));
    return r;
}
__device__ __forceinline__ void fma2(u64& acc, u64 a, u64 b) {
    asm("fma.rn.f32x2 %0, %1, %2, %0;" : "+l"(acc) : "l"(a), "l"(b));
}
// u64 f32-pair -> packed half2 word
__device__ __forceinline__ unsigned pair_to_h2(u64 a) {
    float lo, hi;
    asm("mov.b64 {%0, %1}, %2;" : "=f"(lo), "=f"(hi) : "l"(a));
    unsigned r;
    asm("cvt.rn.f16x2.f32 %0, %1, %2;" : "=r"(r) : "f"(hi), "f"(lo));
    return r;
}
__device__ __forceinline__ float2 h2_to_f2(unsigned u) {
    __half2 h = *reinterpret_cast<__half2*>(&u);
    return __half22float2(h);
}

// ---------------- setup ----------------------------------------------------
__global__ void initKernel(const int* __restrict__ ei) {
    int i = blockIdx.x * blockDim.x + threadIdx.x;
    if (i < NNODES) d_cnt[i] = 0;
    if (i == 0) {
        int allzero = 1;
        for (int k = 0; k < 64; k++)
            if (ei[2 * k + 1] != 0) { allzero = 0; break; }
        d_is64 = allzero;          // int64 values < 2^31: odd words all zero
        d_total = 0;
    }
}

__global__ void countDegKernel(const int* __restrict__ ei, int E) {
    int e = blockIdx.x * blockDim.x + threadIdx.x;
    if (e < E) {
        int stride = d_is64 ? 2 : 1;
        int dst = ei[(size_t)stride * (E + e)];
        if ((unsigned)dst < NNODES) atomicAdd(&d_cnt[dst], 1);
    }
}

__global__ void baseKernel() {
    int n = blockIdx.x * blockDim.x + threadIdx.x;
    if (n < NNODES) {
        int c = d_cnt[n];
        int base = atomicAdd(&d_total, c);
        d_beg[n] = base;
        d_cur[n] = base;
        d_dinv[n] = rsqrtf((float)(c + 1));   // +1 for self loop
    }
}

__global__ void fillCsrKernel(const int* __restrict__ ei, int E) {
    int e = blockIdx.x * blockDim.x + threadIdx.x;
    if (e < E) {
        int stride = d_is64 ? 2 : 1;
        int src = ei[(size_t)stride * e];
        int dst = ei[(size_t)stride * (E + e)];
        if ((unsigned)src < NNODES && (unsigned)dst < NNODES) {
            int p = atomicAdd(&d_cur[dst], 1);
            if ((unsigned)p < EMAX) d_csr[p] = src;
        }
    }
}

// ---------------- GEMM core with packed fp32x2, fp16 output ----------------
// block = 4 nodes x 8 batches = 32 rows, 128 cols, 256 threads.
// thread: 4 rows x 4 cols; accumulators held as f32x2 pairs; store as half2x2.
__device__ __forceinline__ void gemm_core_h(const float4 xs4[32][32],
                                            const ulonglong2* __restrict__ Wv,
                                            uint2* __restrict__ outh,
                                            int n0, int t) {
    int c4 = t & 31;                  // col group: cols 4*c4 .. 4*c4+3
    int rg = t >> 5;                  // row group: rows rg*4 .. rg*4+3
    u64 acc[4][2];
#pragma unroll
    for (int r = 0; r < 4; r++) { acc[r][0] = 0ull; acc[r][1] = 0ull; }

    for (int f4 = 0; f4 < 32; f4++) {
        ulonglong2 w0 = Wv[(4 * f4 + 0) * 32 + c4];
        ulonglong2 w1 = Wv[(4 * f4 + 1) * 32 + c4];
        ulonglong2 w2 = Wv[(4 * f4 + 2) * 32 + c4];
        ulonglong2 w3 = Wv[(4 * f4 + 3) * 32 + c4];
#pragma unroll
        for (int rr = 0; rr < 4; rr++) {
            float4 xv = xs4[rg * 4 + rr][f4];
            u64 dA = pack_dup(xv.x);
            u64 dB = pack_dup(xv.y);
            u64 dC = pack_dup(xv.z);
            u64 dD = pack_dup(xv.w);
            fma2(acc[rr][0], dA, w0.x); fma2(acc[rr][1], dA, w0.y);
            fma2(acc[rr][0], dB, w1.x); fma2(acc[rr][1], dB, w1.y);
            fma2(acc[rr][0], dC, w2.x); fma2(acc[rr][1], dC, w2.y);
            fma2(acc[rr][0], dD, w3.x); fma2(acc[rr][1], dD, w3.y);
        }
    }

#pragma unroll
    for (int rr = 0; rr < 4; rr++) {
        int r = rg * 4 + rr;
        int i = r >> 3;
        int b = r & 7;
        uint2 v;
        v.x = pair_to_h2(acc[rr][0]);
        v.y = pair_to_h2(acc[rr][1]);
        outh[((size_t)(n0 + i) * NB + b) * 32 + c4] = v;
    }
}

__global__ void __launch_bounds__(256) gemm1Kernel(const float4* __restrict__ x4,
                                                   const ulonglong2* __restrict__ Wv) {
    __shared__ float4 xs4[32][32];
    int n0 = blockIdx.x * 4;
    int t = threadIdx.x;
#pragma unroll
    for (int k = 0; k < 4; k++) {
        int e = k * 256 + t;
        int r = e >> 5, f4 = e & 31;
        int i = r >> 3, b = r & 7;
        xs4[r][f4] = x4[((size_t)b * NNODES + (n0 + i)) * 32 + f4];
    }
    __syncthreads();
    gemm_core_h(xs4, Wv, d_t1, n0, t);
}

__global__ void __launch_bounds__(256) gemm2Kernel(const ulonglong2* __restrict__ Wv) {
    __shared__ float4 xs4[32][32];
    int n0 = blockIdx.x * 4;
    int t = threadIdx.x;
#pragma unroll
    for (int k = 0; k < 4; k++) {
        int e = k * 256 + t;
        int r = e >> 5, f4 = e & 31;
        int i = r >> 3, b = r & 7;
        xs4[r][f4] = d_h1[((size_t)(n0 + i) * NB + b) * 32 + f4];
    }
    __syncthreads();
    gemm_core_h(xs4, Wv, d_t2, n0, t);
}

// ---------------- aggregation: fp16 gather, fp32 accumulate ----------------
// one block of 256 threads per node; thread c4 owns cols 4*c4 .. 4*c4+3.
__device__ __forceinline__ float4 agg_gather_h(const uint2* __restrict__ tin,
                                               int n, int c4) {
    float dn = d_dinv[n];
    int beg = d_beg[n];
    int end = beg + d_cnt[n];
    float4 a0 = {0.f, 0.f, 0.f, 0.f};
    float4 a1 = {0.f, 0.f, 0.f, 0.f};
    float4 a2 = {0.f, 0.f, 0.f, 0.f};
    float4 a3 = {0.f, 0.f, 0.f, 0.f};
    int e = beg;
    for (; e + 4 <= end; e += 4) {
        int s0 = d_csr[e + 0];
        int s1 = d_csr[e + 1];
        int s2 = d_csr[e + 2];
        int s3 = d_csr[e + 3];
        float w0 = d_dinv[s0];
        float w1 = d_dinv[s1];
        float w2 = d_dinv[s2];
        float w3 = d_dinv[s3];
        uint2 p0 = tin[(size_t)s0 * BH4 + c4];
        uint2 p1 = tin[(size_t)s1 * BH4 + c4];
        uint2 p2 = tin[(size_t)s2 * BH4 + c4];
        uint2 p3 = tin[(size_t)s3 * BH4 + c4];
        float2 f0a = h2_to_f2(p0.x), f0b = h2_to_f2(p0.y);
        float2 f1a = h2_to_f2(p1.x), f1b = h2_to_f2(p1.y);
        float2 f2a = h2_to_f2(p2.x), f2b = h2_to_f2(p2.y);
        float2 f3a = h2_to_f2(p3.x), f3b = h2_to_f2(p3.y);
        a0.x += w0 * f0a.x; a0.y += w0 * f0a.y; a0.z += w0 * f0b.x; a0.w += w0 * f0b.y;
        a1.x += w1 * f1a.x; a1.y += w1 * f1a.y; a1.z += w1 * f1b.x; a1.w += w1 * f1b.y;
        a2.x += w2 * f2a.x; a2.y += w2 * f2a.y; a2.z += w2 * f2b.x; a2.w += w2 * f2b.y;
        a3.x += w3 * f3a.x; a3.y += w3 * f3a.y; a3.z += w3 * f3b.x; a3.w += w3 * f3b.y;
    }
    for (; e < end; e++) {
        int s = d_csr[e];
        float w = d_dinv[s];
        uint2 p = tin[(size_t)s * BH4 + c4];
        float2 fa = h2_to_f2(p.x), fb = h2_to_f2(p.y);
        a0.x += w * fa.x; a0.y += w * fa.y; a0.z += w * fb.x; a0.w += w * fb.y;
    }
    uint2 ps = tin[(size_t)n * BH4 + c4];
    float2 sa = h2_to_f2(ps.x), sb = h2_to_f2(ps.y);
    float sw = dn * dn;
    float4 r;
    r.x = ((a0.x + a1.x) + (a2.x + a3.x)) * dn + sw * sa.x;
    r.y = ((a0.y + a1.y) + (a2.y + a3.y)) * dn + sw * sa.y;
    r.z = ((a0.z + a1.z) + (a2.z + a3.z)) * dn + sw * sb.x;
    r.w = ((a0.w + a1.w) + (a2.w + a3.w)) * dn + sw * sb.y;
    return r;
}

__global__ void __launch_bounds__(256) aggReluKernel(const float4* __restrict__ bias4) {
    int n = blockIdx.x;
    int c4 = threadIdx.x;                    // cols 4*c4..4*c4+3 of 1024
    float4 v = agg_gather_h(d_t1, n, c4);
    float4 bb = bias4[c4 & 31];              // bias over h = col % 128
    v.x = fmaxf(v.x + bb.x, 0.f);
    v.y = fmaxf(v.y + bb.y, 0.f);
    v.z = fmaxf(v.z + bb.z, 0.f);
    v.w = fmaxf(v.w + bb.w, 0.f);
    d_h1[(size_t)n * BH4 + c4] = v;          // fp32: feeds GEMM2 at full precision
}

// warp w owns row (n, b=w): lanes hold h = 4*lane .. 4*lane+3
__global__ void __launch_bounds__(256) aggLNKernel(const float4* __restrict__ bias4,
                                                   const float4* __restrict__ lnw4,
                                                   const float4* __restrict__ lnb4,
                                                   float4* __restrict__ out4) {
    int n = blockIdx.x;
    int t = threadIdx.x;
    int lane = t & 31;
    int b = t >> 5;
    float4 v = agg_gather_h(d_t2, n, t);
    float4 bb = bias4[lane];
    v.x += bb.x; v.y += bb.y; v.z += bb.z; v.w += bb.w;

    float s = (v.x + v.y) + (v.z + v.w);
#pragma unroll
    for (int off = 16; off > 0; off >>= 1) s += __shfl_xor_sync(0xffffffffu, s, off);
    float mean = s * (1.f / 128.f);

    float4 d;
    d.x = v.x - mean; d.y = v.y - mean; d.z = v.z - mean; d.w = v.w - mean;
    float s2 = (d.x * d.x + d.y * d.y) + (d.z * d.z + d.w * d.w);
#pragma unroll
    for (int off = 16; off > 0; off >>= 1) s2 += __shfl_xor_sync(0xffffffffu, s2, off);
    float rs = rsqrtf(s2 * (1.f / 128.f) + 1e-5f);

    float4 w = lnw4[lane];
    float4 bo = lnb4[lane];
    float4 r;
    r.x = d.x * rs * w.x + bo.x;
    r.y = d.y * rs * w.y + bo.y;
    r.z = d.z * rs * w.z + bo.z;
    r.w = d.w * rs * w.w + bo.w;
    out4[((size_t)b * NNODES + n) * 32 + lane] = r;
}

// ---------------- launch ---------------------------------------------------
extern "C" void kernel_launch(void* const* d_in, const int* in_sizes, int n_in,
                              void* d_out, int out_size) {
    const float4*     x4  = (const float4*)d_in[0];
    const int*        ei  = (const int*)d_in[1];     // int32 OR int64 (auto)
    const ulonglong2* W1  = (const ulonglong2*)d_in[2];
    const float4*     b1  = (const float4*)d_in[3];
    const ulonglong2* W2  = (const ulonglong2*)d_in[4];
    const float4*     b2  = (const float4*)d_in[5];
    const float4*     lnw = (const float4*)d_in[6];
    const float4*     lnb = (const float4*)d_in[7];
    float4*           out = (float4*)d_out;

    int E = in_sizes[1] / 2;
    if (E > EMAX) E = EMAX;

    initKernel<<<(NNODES + 255) / 256, 256>>>(ei);
    countDegKernel<<<(E + 255) / 256, 256>>>(ei, E);
    baseKernel<<<(NNODES + 255) / 256, 256>>>();
    fillCsrKernel<<<(E + 255) / 256, 256>>>(ei, E);

    gemm1Kernel<<<NNODES / 4, 256>>>(x4, W1);
    aggReluKernel<<<NNODES, 256>>>(b1);
    gemm2Kernel<<<NNODES / 4, 256>>>(W2);
    aggLNKernel<<<NNODES, 256>>>(b2, lnw, lnb, out);
}

// round 8
// speedup vs baseline: 3.3431x; 1.3969x over previous
#include <cuda_runtime.h>
#include <cuda_fp16.h>

// GNNEncoder: B=8, N=10000, F_IN=128, H=128, E=160000
#define NB     8
#define NNODES 10000
#define HDIM   128
#define BH     (NB * HDIM)        // 1024
#define BH4    (BH / 4)           // 256 groups of 4 cols per node row
#define EMAX   160000
#define ROWS   (NNODES * NB)      // 80000 gemm rows (node-major: r = n*8+b)

// ---------------- device scratch -------------------------------------------
__device__ uint2  d_t1[NNODES * BH4];   // fp16 x4, dinv-prescaled gather rows
__device__ float4 d_h1[NNODES * BH4];   // fp32 relu(agg1+b1): GEMM2 input
__device__ uint2  d_t2[NNODES * BH4];   // fp16 x4, dinv-prescaled
__device__ __align__(16) uint2 d_w1f[16 * 16 * 32];  // W1 tf32 frag [kk][ct][lane]
__device__ __align__(16) uint2 d_w2f[16 * 16 * 32];
__device__ int    d_cnt[NNODES];
__device__ int    d_beg[NNODES];
__device__ int    d_cur[NNODES];
__device__ float  d_dinv[NNODES];
__device__ int    d_csr[EMAX];
__device__ int    d_total;
__device__ int    d_is64;

// ---------------- helpers --------------------------------------------------
__device__ __forceinline__ unsigned f2tf32(float x) {
    unsigned r;
    asm("cvt.rna.tf32.f32 %0, %1;" : "=r"(r) : "f"(x));
    return r;
}
__device__ __forceinline__ unsigned f2_to_h2(float lo, float hi) {
    unsigned r;
    asm("cvt.rn.f16x2.f32 %0, %1, %2;" : "=r"(r) : "f"(hi), "f"(lo));
    return r;
}
__device__ __forceinline__ float2 h2_to_f2(unsigned u) {
    __half2 h = *reinterpret_cast<__half2*>(&u);
    return __half22float2(h);
}
__device__ __forceinline__ void mma_tf32(float* c, unsigned a0, unsigned a1,
                                         unsigned a2, unsigned a3,
                                         unsigned b0, unsigned b1) {
    asm("mma.sync.aligned.m16n8k8.row.col.f32.tf32.tf32.f32 "
        "{%0,%1,%2,%3}, {%4,%5,%6,%7}, {%8,%9}, {%0,%1,%2,%3};"
        : "+f"(c[0]), "+f"(c[1]), "+f"(c[2]), "+f"(c[3])
        : "r"(a0), "r"(a1), "r"(a2), "r"(a3), "r"(b0), "r"(b1));
}

// ---------------- setup ----------------------------------------------------
// Pre-convert W (128x128, [k][n]) into tf32 B-fragment order:
// frag[kk][ct][lane] = (B[k=kk*8+(l&3)][n=ct*8+(l>>2)], B[k+4][n])
__global__ void prepWKernel(const float* __restrict__ W1,
                            const float* __restrict__ W2) {
    int idx = blockIdx.x * blockDim.x + threadIdx.x;   // 0..8191
    int kk = idx >> 9;
    int ct = (idx >> 5) & 15;
    int l = idx & 31;
    int k0 = kk * 8 + (l & 3);
    int n = ct * 8 + (l >> 2);
    uint2 v1, v2;
    v1.x = f2tf32(W1[k0 * HDIM + n]);
    v1.y = f2tf32(W1[(k0 + 4) * HDIM + n]);
    v2.x = f2tf32(W2[k0 * HDIM + n]);
    v2.y = f2tf32(W2[(k0 + 4) * HDIM + n]);
    d_w1f[idx] = v1;
    d_w2f[idx] = v2;
}

__global__ void initKernel(const int* __restrict__ ei) {
    int i = blockIdx.x * blockDim.x + threadIdx.x;
    if (i < NNODES) d_cnt[i] = 0;
    if (i == 0) {
        int allzero = 1;
        for (int k = 0; k < 64; k++)
            if (ei[2 * k + 1] != 0) { allzero = 0; break; }
        d_is64 = allzero;          // int64 values < 2^31: odd words all zero
        d_total = 0;
    }
}

__global__ void countDegKernel(const int* __restrict__ ei, int E) {
    int e = blockIdx.x * blockDim.x + threadIdx.x;
    if (e < E) {
        int stride = d_is64 ? 2 : 1;
        int dst = ei[(size_t)stride * (E + e)];
        if ((unsigned)dst < NNODES) atomicAdd(&d_cnt[dst], 1);
    }
}

__global__ void baseKernel() {
    int n = blockIdx.x * blockDim.x + threadIdx.x;
    if (n < NNODES) {
        int c = d_cnt[n];
        int base = atomicAdd(&d_total, c);
        d_beg[n] = base;
        d_cur[n] = base;
        d_dinv[n] = rsqrtf((float)(c + 1));   // +1 for self loop
    }
}

__global__ void fillCsrKernel(const int* __restrict__ ei, int E) {
    int e = blockIdx.x * blockDim.x + threadIdx.x;
    if (e < E) {
        int stride = d_is64 ? 2 : 1;
        int src = ei[(size_t)stride * e];
        int dst = ei[(size_t)stride * (E + e)];
        if ((unsigned)src < NNODES && (unsigned)dst < NNODES) {
            int p = atomicAdd(&d_cur[dst], 1);
            if ((unsigned)p < EMAX) d_csr[p] = src;
        }
    }
}

// ---------------- tf32 tensor-core GEMM ------------------------------------
// Block = 64 rows (8 nodes x 8 batches, r = n*8+b) x 128 cols, 8 warps.
// Warp w: row-tile (w>>1)*16, col-half (w&1)*64 (8 n8-tiles).
// Output: fp16, prescaled by dinv[node].
__device__ __forceinline__ void gemm_mma(const float* __restrict__ A0base,
                                         const float* __restrict__ A1base,
                                         const uint2* __restrict__ wf,
                                         uint2* __restrict__ outh,
                                         int r0, int r1, int colbase, int lane) {
    int tid = lane & 3;
    float c[8][4];
#pragma unroll
    for (int ct = 0; ct < 8; ct++)
#pragma unroll
        for (int j = 0; j < 4; j++) c[ct][j] = 0.f;

#pragma unroll 4
    for (int kk = 0; kk < 16; kk++) {
        int k0 = kk * 8 + tid;
        unsigned a0 = f2tf32(A0base[k0]);
        unsigned a1 = f2tf32(A1base[k0]);
        unsigned a2 = f2tf32(A0base[k0 + 4]);
        unsigned a3 = f2tf32(A1base[k0 + 4]);
        const uint2* wrow = wf + kk * 512 + lane;
#pragma unroll
        for (int ct = 0; ct < 8; ct++) {
            uint2 b = wrow[ct * 32];
            mma_tf32(c[ct], a0, a1, a2, a3, b.x, b.y);
        }
    }

    float s0 = d_dinv[r0 >> 3];
    float s1 = d_dinv[r1 >> 3];
    unsigned* outp = (unsigned*)outh;
#pragma unroll
    for (int ct = 0; ct < 8; ct++) {
        int h = colbase + ct * 8 + tid * 2;
        outp[(size_t)r0 * 64 + (h >> 1)] = f2_to_h2(c[ct][0] * s0, c[ct][1] * s0);
        outp[(size_t)r1 * 64 + (h >> 1)] = f2_to_h2(c[ct][2] * s1, c[ct][3] * s1);
    }
}

__global__ void __launch_bounds__(256) gemm1Kernel(const float* __restrict__ x) {
    int t = threadIdx.x;
    int w = t >> 5;
    int lane = t & 31;
    int rbase = blockIdx.x * 64 + (w >> 1) * 16;
    int colbase = (w & 1) * 64;
    int gid = lane >> 2;
    int r0 = rbase + gid;
    int r1 = r0 + 8;
    // x layout [b][n][f]: row r = n*8+b
    const float* A0 = x + ((size_t)(r0 & 7) * NNODES + (r0 >> 3)) * HDIM;
    const float* A1 = x + ((size_t)(r1 & 7) * NNODES + (r1 >> 3)) * HDIM;
    const uint2* wf = d_w1f + (w & 1) * 8 * 32;   // col-half offset (ct base)
    gemm_mma(A0, A1, wf, d_t1, r0, r1, colbase, lane);
}

__global__ void __launch_bounds__(256) gemm2Kernel() {
    int t = threadIdx.x;
    int w = t >> 5;
    int lane = t & 31;
    int rbase = blockIdx.x * 64 + (w >> 1) * 16;
    int colbase = (w & 1) * 64;
    int gid = lane >> 2;
    int r0 = rbase + gid;
    int r1 = r0 + 8;
    const float* h1 = (const float*)d_h1;         // [r][128] contiguous
    const float* A0 = h1 + (size_t)r0 * HDIM;
    const float* A1 = h1 + (size_t)r1 * HDIM;
    const uint2* wf = d_w2f + (w & 1) * 8 * 32;
    gemm_mma(A0, A1, wf, d_t2, r0, r1, colbase, lane);
}

// ---------------- aggregation: prescaled fp16 gather, fp32 accumulate ------
// one block of 256 threads per node; thread c4 owns cols 4*c4 .. 4*c4+3.
// returns dn * (sum over edges + self) of prescaled rows.
__device__ __forceinline__ float4 agg_sum(const uint2* __restrict__ tin,
                                          int n, int c4) {
    int beg = d_beg[n];
    int end = beg + d_cnt[n];
    uint2 ps = tin[(size_t)n * BH4 + c4];          // self (prescaled)
    float2 sa = h2_to_f2(ps.x), sb = h2_to_f2(ps.y);
    float4 A = {sa.x, sa.y, sb.x, sb.y};
    float4 Bc = {0.f, 0.f, 0.f, 0.f};
    int e = beg;
    for (; e + 8 <= end; e += 8) {
        int s0 = d_csr[e + 0], s1 = d_csr[e + 1];
        int s2 = d_csr[e + 2], s3 = d_csr[e + 3];
        int s4 = d_csr[e + 4], s5 = d_csr[e + 5];
        int s6 = d_csr[e + 6], s7 = d_csr[e + 7];
        uint2 p0 = tin[(size_t)s0 * BH4 + c4];
        uint2 p1 = tin[(size_t)s1 * BH4 + c4];
        uint2 p2 = tin[(size_t)s2 * BH4 + c4];
        uint2 p3 = tin[(size_t)s3 * BH4 + c4];
        uint2 p4 = tin[(size_t)s4 * BH4 + c4];
        uint2 p5 = tin[(size_t)s5 * BH4 + c4];
        uint2 p6 = tin[(size_t)s6 * BH4 + c4];
        uint2 p7 = tin[(size_t)s7 * BH4 + c4];
        float2 f;
        f = h2_to_f2(p0.x); A.x += f.x; A.y += f.y;
        f = h2_to_f2(p0.y); A.z += f.x; A.w += f.y;
        f = h2_to_f2(p1.x); A.x += f.x; A.y += f.y;
        f = h2_to_f2(p1.y); A.z += f.x; A.w += f.y;
        f = h2_to_f2(p2.x); A.x += f.x; A.y += f.y;
        f = h2_to_f2(p2.y); A.z += f.x; A.w += f.y;
        f = h2_to_f2(p3.x); A.x += f.x; A.y += f.y;
        f = h2_to_f2(p3.y); A.z += f.x; A.w += f.y;
        f = h2_to_f2(p4.x); Bc.x += f.x; Bc.y += f.y;
        f = h2_to_f2(p4.y); Bc.z += f.x; Bc.w += f.y;
        f = h2_to_f2(p5.x); Bc.x += f.x; Bc.y += f.y;
        f = h2_to_f2(p5.y); Bc.z += f.x; Bc.w += f.y;
        f = h2_to_f2(p6.x); Bc.x += f.x; Bc.y += f.y;
        f = h2_to_f2(p6.y); Bc.z += f.x; Bc.w += f.y;
        f = h2_to_f2(p7.x); Bc.x += f.x; Bc.y += f.y;
        f = h2_to_f2(p7.y); Bc.z += f.x; Bc.w += f.y;
    }
    for (; e < end; e++) {
        int s = d_csr[e];
        uint2 p = tin[(size_t)s * BH4 + c4];
        float2 fa = h2_to_f2(p.x), fb = h2_to_f2(p.y);
        A.x += fa.x; A.y += fa.y; A.z += fb.x; A.w += fb.y;
    }
    float dn = d_dinv[n];
    float4 r;
    r.x = (A.x + Bc.x) * dn;
    r.y = (A.y + Bc.y) * dn;
    r.z = (A.z + Bc.z) * dn;
    r.w = (A.w + Bc.w) * dn;
    return r;
}

__global__ void __launch_bounds__(256) aggReluKernel(const float4* __restrict__ bias4) {
    int n = blockIdx.x;
    int c4 = threadIdx.x;
    float4 v = agg_sum(d_t1, n, c4);
    float4 bb = bias4[c4 & 31];
    v.x = fmaxf(v.x + bb.x, 0.f);
    v.y = fmaxf(v.y + bb.y, 0.f);
    v.z = fmaxf(v.z + bb.z, 0.f);
    v.w = fmaxf(v.w + bb.w, 0.f);
    d_h1[(size_t)n * BH4 + c4] = v;          // fp32 GEMM2 input
}

// warp b owns row (n, b): lanes hold h = 4*lane .. 4*lane+3
__global__ void __launch_bounds__(256) aggLNKernel(const float4* __restrict__ bias4,
                                                   const float4* __restrict__ lnw4,
                                                   const float4* __restrict__ lnb4,
                                                   float4* __restrict__ out4) {
    int n = blockIdx.x;
    int t = threadIdx.x;
    int lane = t & 31;
    int b = t >> 5;
    float4 v = agg_sum(d_t2, n, t);
    float4 bb = bias4[lane];
    v.x += bb.x; v.y += bb.y; v.z += bb.z; v.w += bb.w;

    float s = (v.x + v.y) + (v.z + v.w);
#pragma unroll
    for (int off = 16; off > 0; off >>= 1) s += __shfl_xor_sync(0xffffffffu, s, off);
    float mean = s * (1.f / 128.f);

    float4 d;
    d.x = v.x - mean; d.y = v.y - mean; d.z = v.z - mean; d.w = v.w - mean;
    float s2 = (d.x * d.x + d.y * d.y) + (d.z * d.z + d.w * d.w);
#pragma unroll
    for (int off = 16; off > 0; off >>= 1) s2 += __shfl_xor_sync(0xffffffffu, s2, off);
    float rs = rsqrtf(s2 * (1.f / 128.f) + 1e-5f);

    float4 w = lnw4[lane];
    float4 bo = lnb4[lane];
    float4 r;
    r.x = d.x * rs * w.x + bo.x;
    r.y = d.y * rs * w.y + bo.y;
    r.z = d.z * rs * w.z + bo.z;
    r.w = d.w * rs * w.w + bo.w;
    out4[((size_t)b * NNODES + n) * 32 + lane] = r;
}

// ---------------- launch ---------------------------------------------------
extern "C" void kernel_launch(void* const* d_in, const int* in_sizes, int n_in,
                              void* d_out, int out_size) {
    const float*  x   = (const float*)d_in[0];
    const int*    ei  = (const int*)d_in[1];     // int32 OR int64 (auto)
    const float*  W1  = (const float*)d_in[2];
    const float4* b1  = (const float4*)d_in[3];
    const float*  W2  = (const float*)d_in[4];
    const float4* b2  = (const float4*)d_in[5];
    const float4* lnw = (const float4*)d_in[6];
    const float4* lnb = (const float4*)d_in[7];
    float4*       out = (float4*)d_out;

    int E = in_sizes[1] / 2;
    if (E > EMAX) E = EMAX;

    prepWKernel<<<32, 256>>>(W1, W2);
    initKernel<<<(NNODES + 255) / 256, 256>>>(ei);
    countDegKernel<<<(E + 255) / 256, 256>>>(ei, E);
    baseKernel<<<(NNODES + 255) / 256, 256>>>();
    fillCsrKernel<<<(E + 255) / 256, 256>>>(ei, E);

    gemm1Kernel<<<ROWS / 64, 256>>>(x);
    aggReluKernel<<<NNODES, 256>>>(b1);
    gemm2Kernel<<<ROWS / 64, 256>>>();
    aggLNKernel<<<NNODES, 256>>>(b2, lnw, lnb, out);
}

// round 9
// speedup vs baseline: 4.3427x; 1.2990x over previous
#include <cuda_runtime.h>
#include <cuda_fp16.h>

// GNNEncoder: B=8, N=10000, F_IN=128, H=128, E=160000
#define NB     8
#define NNODES 10000
#define HDIM   128
#define BH     (NB * HDIM)        // 1024
#define BH4    (BH / 4)           // 256 groups of 4 cols per node row
#define EMAX   160000
#define ROWS   (NNODES * NB)      // 80000 gemm rows (node-major: r = n*8+b)
#define GEMMBLK 1250              // ROWS / 64
#define CSRBLK  625               // EMAX / 256

// ---------------- device scratch -------------------------------------------
// Invariant: d_cnt[] == 0 and d_total == 0 at entry of every kernel_launch
// (static init supplies the first call; aggLN's tail restores it each call).
__device__ uint2  d_t1[NNODES * BH4];   // fp16 x4, dinv-prescaled gather rows
__device__ float4 d_h1[NNODES * BH4];   // fp32 relu(agg1+b1): GEMM2 input
__device__ uint2  d_t2[NNODES * BH4];   // fp16 x4, dinv-prescaled
__device__ __align__(16) uint2 d_w1f[16 * 16 * 32];  // W tf32 frag [kk][ct][lane]
__device__ __align__(16) uint2 d_w2f[16 * 16 * 32];
__device__ int    d_cnt[NNODES];
__device__ int    d_beg[NNODES];
__device__ int    d_cur[NNODES];
__device__ float  d_dinv[NNODES];
__device__ int    d_csr[EMAX];
__device__ int    d_total;

// ---------------- helpers --------------------------------------------------
__device__ __forceinline__ unsigned f2tf32(float x) {
    unsigned r;
    asm("cvt.rna.tf32.f32 %0, %1;" : "=r"(r) : "f"(x));
    return r;
}
__device__ __forceinline__ unsigned f2_to_h2(float lo, float hi) {
    unsigned r;
    asm("cvt.rn.f16x2.f32 %0, %1, %2;" : "=r"(r) : "f"(hi), "f"(lo));
    return r;
}
__device__ __forceinline__ float2 h2_to_f2(unsigned u) {
    __half2 h = *reinterpret_cast<__half2*>(&u);
    return __half22float2(h);
}
__device__ __forceinline__ void mma_tf32(float* c, unsigned a0, unsigned a1,
                                         unsigned a2, unsigned a3,
                                         unsigned b0, unsigned b1) {
    asm("mma.sync.aligned.m16n8k8.row.col.f32.tf32.tf32.f32 "
        "{%0,%1,%2,%3}, {%4,%5,%6,%7}, {%8,%9}, {%0,%1,%2,%3};"
        : "+f"(c[0]), "+f"(c[1]), "+f"(c[2]), "+f"(c[3])
        : "r"(a0), "r"(a1), "r"(a2), "r"(a3), "r"(b0), "r"(b1));
}
// int64 buffers hold values < 2^31 -> odd 32-bit words are all zero.
// 8 uniform (broadcast) probes; false-positive prob for int32 data ~1e-32.
__device__ __forceinline__ int detect64(const int* __restrict__ ei) {
    return ((ei[1] | ei[3] | ei[5] | ei[7] |
             ei[9] | ei[11] | ei[13] | ei[15]) == 0) ? 2 : 1;  // word stride
}

// ---------------- kernel 1: degree count + W fragment prep -----------------
// blocks [0, CSRBLK): count degrees. blocks [CSRBLK, CSRBLK+32): prep W frags.
// frag[kk][ct][lane] = (W[k=kk*8+(l&3)][n=ct*8+(l>>2)], W[k+4][n]) as tf32.
__global__ void __launch_bounds__(256) countPrepKernel(const int* __restrict__ ei,
                                                       const float* __restrict__ W1,
                                                       const float* __restrict__ W2,
                                                       int E) {
    int blk = blockIdx.x;
    int t = threadIdx.x;
    if (blk < CSRBLK) {
        int e = blk * 256 + t;
        if (e < E) {
            int stride = detect64(ei);
            int dst = ei[(size_t)stride * (E + e)];
            if ((unsigned)dst < NNODES) atomicAdd(&d_cnt[dst], 1);
        }
    } else {
        int idx = (blk - CSRBLK) * 256 + t;   // 0..8191
        int kk = idx >> 9;
        int ct = (idx >> 5) & 15;
        int l = idx & 31;
        int k0 = kk * 8 + (l & 3);
        int n = ct * 8 + (l >> 2);
        uint2 v1, v2;
        v1.x = f2tf32(W1[k0 * HDIM + n]);
        v1.y = f2tf32(W1[(k0 + 4) * HDIM + n]);
        v2.x = f2tf32(W2[k0 * HDIM + n]);
        v2.y = f2tf32(W2[(k0 + 4) * HDIM + n]);
        d_w1f[idx] = v1;
        d_w2f[idx] = v2;
    }
}

// ---------------- kernel 2: CSR base offsets + dinv -------------------------
__global__ void baseKernel() {
    int n = blockIdx.x * blockDim.x + threadIdx.x;
    if (n < NNODES) {
        int c = d_cnt[n];
        int base = atomicAdd(&d_total, c);
        d_beg[n] = base;
        d_cur[n] = base;
        d_dinv[n] = rsqrtf((float)(c + 1));   // +1 for self loop
    }
}

// ---------------- tf32 MMA core over smem-staged A --------------------------
// xs[64][132]: 64 rows x 128 floats, pad 4 -> bank(132r+k)= (4r+k)%32,
// conflict-free for (8 rows x 4 k-lanes) fragment reads.
// Warp w: row-tile (w>>1)*16 (local), col-half (w&1)*64. Output fp16,
// prescaled by dinv[node], node = global_row >> 3.
__device__ __forceinline__ void gemm_mma_smem(const float xs[64][132],
                                              const uint2* __restrict__ wf,
                                              uint2* __restrict__ outh,
                                              int grbase, int w, int lane) {
    int tid = lane & 3;
    int gid = lane >> 2;
    int r0l = (w >> 1) * 16 + gid;
    int r1l = r0l + 8;
    int colbase = (w & 1) * 64;
    const uint2* wfh = wf + (w & 1) * 256;   // ct-half offset (8 tiles x 32)

    float c[8][4];
#pragma unroll
    for (int ct = 0; ct < 8; ct++)
#pragma unroll
        for (int j = 0; j < 4; j++) c[ct][j] = 0.f;

#pragma unroll 4
    for (int kk = 0; kk < 16; kk++) {
        int k0 = kk * 8 + tid;
        unsigned a0 = f2tf32(xs[r0l][k0]);
        unsigned a1 = f2tf32(xs[r1l][k0]);
        unsigned a2 = f2tf32(xs[r0l][k0 + 4]);
        unsigned a3 = f2tf32(xs[r1l][k0 + 4]);
        const uint2* wrow = wfh + kk * 512 + lane;
#pragma unroll
        for (int ct = 0; ct < 8; ct++) {
            uint2 b = wrow[ct * 32];
            mma_tf32(c[ct], a0, a1, a2, a3, b.x, b.y);
        }
    }

    int gr0 = grbase + r0l;
    int gr1 = grbase + r1l;
    float s0 = d_dinv[gr0 >> 3];
    float s1 = d_dinv[gr1 >> 3];
    unsigned* outp = (unsigned*)outh;
#pragma unroll
    for (int ct = 0; ct < 8; ct++) {
        int h = colbase + ct * 8 + tid * 2;
        outp[(size_t)gr0 * 64 + (h >> 1)] = f2_to_h2(c[ct][0] * s0, c[ct][1] * s0);
        outp[(size_t)gr1 * 64 + (h >> 1)] = f2_to_h2(c[ct][2] * s1, c[ct][3] * s1);
    }
}

// ---------------- kernel 3: GEMM1 (x @ W1) fused with CSR fill --------------
// blocks [0, GEMMBLK): gemm over 64 rows. blocks [GEMMBLK, +CSRBLK): fill CSR.
__global__ void __launch_bounds__(256) gemm1CsrKernel(const float4* __restrict__ x4,
                                                      const int* __restrict__ ei,
                                                      int E) {
    __shared__ float xs[64][132];
    int t = threadIdx.x;
    if (blockIdx.x < GEMMBLK) {
        int grbase = blockIdx.x * 64;
        // stage: x layout [b][n][f]; row r = n*8 + b
#pragma unroll
        for (int it = 0; it < 8; it++) {
            int e = it * 256 + t;
            int r = e >> 5, f4 = e & 31;
            int gr = grbase + r;
            float4 v = x4[((size_t)(gr & 7) * NNODES + (gr >> 3)) * 32 + f4];
            *(float4*)&xs[r][f4 * 4] = v;    // 528-byte rows: 16B aligned
        }
        __syncthreads();
        gemm_mma_smem(xs, d_w1f, d_t1, grbase, t >> 5, t & 31);
    } else {
        int e = (blockIdx.x - GEMMBLK) * 256 + t;
        if (e < E) {
            int stride = detect64(ei);
            int src = ei[(size_t)stride * e];
            int dst = ei[(size_t)stride * (E + e)];
            if ((unsigned)src < NNODES && (unsigned)dst < NNODES) {
                int p = atomicAdd(&d_cur[dst], 1);
                if ((unsigned)p < EMAX) d_csr[p] = src;
            }
        }
    }
}

// ---------------- kernel 5: GEMM2 (h1 @ W2) --------------------------------
__global__ void __launch_bounds__(256) gemm2Kernel() {
    __shared__ float xs[64][132];
    int t = threadIdx.x;
    int grbase = blockIdx.x * 64;
    const float4* h4 = (const float4*)d_h1;   // [r][128] contiguous
#pragma unroll
    for (int it = 0; it < 8; it++) {
        int e = it * 256 + t;
        int r = e >> 5, f4 = e & 31;
        *(float4*)&xs[r][f4 * 4] = h4[(size_t)(grbase + r) * 32 + f4];
    }
    __syncthreads();
    gemm_mma_smem(xs, d_w2f, d_t2, grbase, t >> 5, t & 31);
}

// ---------------- aggregation: prescaled fp16 gather, fp32 accumulate ------
__device__ __forceinline__ float4 agg_sum(const uint2* __restrict__ tin,
                                          int n, int c4) {
    int beg = d_beg[n];
    int end = beg + d_cnt[n];
    uint2 ps = tin[(size_t)n * BH4 + c4];          // self (prescaled)
    float2 sa = h2_to_f2(ps.x), sb = h2_to_f2(ps.y);
    float4 A = {sa.x, sa.y, sb.x, sb.y};
    float4 Bc = {0.f, 0.f, 0.f, 0.f};
    int e = beg;
    for (; e + 8 <= end; e += 8) {
        int s0 = d_csr[e + 0], s1 = d_csr[e + 1];
        int s2 = d_csr[e + 2], s3 = d_csr[e + 3];
        int s4 = d_csr[e + 4], s5 = d_csr[e + 5];
        int s6 = d_csr[e + 6], s7 = d_csr[e + 7];
        uint2 p0 = tin[(size_t)s0 * BH4 + c4];
        uint2 p1 = tin[(size_t)s1 * BH4 + c4];
        uint2 p2 = tin[(size_t)s2 * BH4 + c4];
        uint2 p3 = tin[(size_t)s3 * BH4 + c4];
        uint2 p4 = tin[(size_t)s4 * BH4 + c4];
        uint2 p5 = tin[(size_t)s5 * BH4 + c4];
        uint2 p6 = tin[(size_t)s6 * BH4 + c4];
        uint2 p7 = tin[(size_t)s7 * BH4 + c4];
        float2 f;
        f = h2_to_f2(p0.x); A.x += f.x; A.y += f.y;
        f = h2_to_f2(p0.y); A.z += f.x; A.w += f.y;
        f = h2_to_f2(p1.x); A.x += f.x; A.y += f.y;
        f = h2_to_f2(p1.y); A.z += f.x; A.w += f.y;
        f = h2_to_f2(p2.x); A.x += f.x; A.y += f.y;
        f = h2_to_f2(p2.y); A.z += f.x; A.w += f.y;
        f = h2_to_f2(p3.x); A.x += f.x; A.y += f.y;
        f = h2_to_f2(p3.y); A.z += f.x; A.w += f.y;
        f = h2_to_f2(p4.x); Bc.x += f.x; Bc.y += f.y;
        f = h2_to_f2(p4.y); Bc.z += f.x; Bc.w += f.y;
        f = h2_to_f2(p5.x); Bc.x += f.x; Bc.y += f.y;
        f = h2_to_f2(p5.y); Bc.z += f.x; Bc.w += f.y;
        f = h2_to_f2(p6.x); Bc.x += f.x; Bc.y += f.y;
        f = h2_to_f2(p6.y); Bc.z += f.x; Bc.w += f.y;
        f = h2_to_f2(p7.x); Bc.x += f.x; Bc.y += f.y;
        f = h2_to_f2(p7.y); Bc.z += f.x; Bc.w += f.y;
    }
    for (; e < end; e++) {
        int s = d_csr[e];
        uint2 p = tin[(size_t)s * BH4 + c4];
        float2 fa = h2_to_f2(p.x), fb = h2_to_f2(p.y);
        A.x += fa.x; A.y += fa.y; A.z += fb.x; A.w += fb.y;
    }
    float dn = d_dinv[n];
    float4 r;
    r.x = (A.x + Bc.x) * dn;
    r.y = (A.y + Bc.y) * dn;
    r.z = (A.z + Bc.z) * dn;
    r.w = (A.w + Bc.w) * dn;
    return r;
}

// kernel 4
__global__ void __launch_bounds__(256) aggReluKernel(const float4* __restrict__ bias4) {
    int n = blockIdx.x;
    int c4 = threadIdx.x;
    float4 v = agg_sum(d_t1, n, c4);
    float4 bb = bias4[c4 & 31];
    v.x = fmaxf(v.x + bb.x, 0.f);
    v.y = fmaxf(v.y + bb.y, 0.f);
    v.z = fmaxf(v.z + bb.z, 0.f);
    v.w = fmaxf(v.w + bb.w, 0.f);
    d_h1[(size_t)n * BH4 + c4] = v;          // fp32 GEMM2 input
}

// kernel 6: agg + LayerNorm; warp b owns row (n, b), lanes hold h=4*lane..+3.
// Tail restores the d_cnt/d_total == 0 invariant for the next replay.
__global__ void __launch_bounds__(256) aggLNKernel(const float4* __restrict__ bias4,
                                                   const float4* __restrict__ lnw4,
                                                   const float4* __restrict__ lnb4,
                                                   float4* __restrict__ out4) {
    int n = blockIdx.x;
    int t = threadIdx.x;
    int lane = t & 31;
    int b = t >> 5;
    float4 v = agg_sum(d_t2, n, t);
    float4 bb = bias4[lane];
    v.x += bb.x; v.y += bb.y; v.z += bb.z; v.w += bb.w;

    float s = (v.x + v.y) + (v.z + v.w);
#pragma unroll
    for (int off = 16; off > 0; off >>= 1) s += __shfl_xor_sync(0xffffffffu, s, off);
    float mean = s * (1.f / 128.f);

    float4 d;
    d.x = v.x - mean; d.y = v.y - mean; d.z = v.z - mean; d.w = v.w - mean;
    float s2 = (d.x * d.x + d.y * d.y) + (d.z * d.z + d.w * d.w);
#pragma unroll
    for (int off = 16; off > 0; off >>= 1) s2 += __shfl_xor_sync(0xffffffffu, s2, off);
    float rs = rsqrtf(s2 * (1.f / 128.f) + 1e-5f);

    float4 w = lnw4[lane];
    float4 bo = lnb4[lane];
    float4 r;
    r.x = d.x * rs * w.x + bo.x;
    r.y = d.y * rs * w.y + bo.y;
    r.z = d.z * rs * w.z + bo.z;
    r.w = d.w * rs * w.w + bo.w;
    out4[((size_t)b * NNODES + n) * 32 + lane] = r;

    // restore invariant (after all threads' agg_sum reads of d_cnt[n])
    __syncthreads();
    if (t == 0) d_cnt[n] = 0;
    if (n == 0 && t == 1) d_total = 0;
}

// ---------------- launch ---------------------------------------------------
extern "C" void kernel_launch(void* const* d_in, const int* in_sizes, int n_in,
                              void* d_out, int out_size) {
    const float4* x4  = (const float4*)d_in[0];
    const int*    ei  = (const int*)d_in[1];     // int32 OR int64 (auto)
    const float*  W1  = (const float*)d_in[2];
    const float4* b1  = (const float4*)d_in[3];
    const float*  W2  = (const float*)d_in[4];
    const float4* b2  = (const float4*)d_in[5];
    const float4* lnw = (const float4*)d_in[6];
    const float4* lnb = (const float4*)d_in[7];
    float4*       out = (float4*)d_out;

    int E = in_sizes[1] / 2;
    if (E > EMAX) E = EMAX;

    countPrepKernel<<<CSRBLK + 32, 256>>>(ei, W1, W2, E);
    baseKernel<<<(NNODES + 255) / 256, 256>>>();
    gemm1CsrKernel<<<GEMMBLK + CSRBLK, 256>>>(x4, ei, E);
    aggReluKernel<<<NNODES, 256>>>(b1);
    gemm2Kernel<<<GEMMBLK, 256>>>();
    aggLNKernel<<<NNODES, 256>>>(b2, lnw, lnb, out);
}